// round 8
// baseline (speedup 1.0000x reference)
#include <cuda_runtime.h>
#include <cuda_fp16.h>
#include <mma.h>
#include <cstdint>
#include <cstddef>

using namespace nvcuda;

#define NB   32
#define NC   256
#define NHW  3136
#define NWID 56
#define NOC  256
#define NR   64
#define NM1  576   // 9 taps * 64 rank

// Device-global scratch (alloc-guard workaround)
__device__ __half g_St[(size_t)NB * NHW * NM1];   // S transposed: [b][p][m] (115 MB) fp16
__device__ __half g_Xh[(size_t)NB * NC * NHW];    // X: [b][c][p] (51 MB) fp16
__device__ __half g_Vh[(size_t)NM1 * NC];         // V: [m][c] fp16
__device__ __half g_U2h[(size_t)NOC * NM1];       // U: [o][m] fp16

// ---------------- helpers ----------------
__device__ __forceinline__ uint32_t smem_u32(const void* p) {
    uint32_t a;
    asm("{ .reg .u64 t; cvta.to.shared.u64 t, %1; cvt.u32.u64 %0, t; }" : "=r"(a) : "l"(p));
    return a;
}
__device__ __forceinline__ void cp16(uint32_t dst, const void* src, int szbytes) {
    asm volatile("cp.async.ca.shared.global [%0], [%1], 16, %2;"
                 :: "r"(dst), "l"(src), "r"(szbytes) : "memory");
}
#define CP_COMMIT() asm volatile("cp.async.commit_group;" ::: "memory")
#define CP_WAIT2()  asm volatile("cp.async.wait_group 2;" ::: "memory")
#define CP_WAIT1()  asm volatile("cp.async.wait_group 1;" ::: "memory")
#define CP_WAIT0()  asm volatile("cp.async.wait_group 0;" ::: "memory")

// ---- gemm1 smem (halves): A 128x72, B 64x136, 3-stage ----
#define LDA 72
#define LDB 136
#define A_OFF(s) ((s) * (128 * LDA))
#define B_OFF(s) (3 * 128 * LDA + (s) * (64 * LDB))
#define DYNSMEM1 ((3 * 128 * LDA + 3 * 64 * LDB) * 2)   // 107520 B (epilogue T 67584 fits)
#define LDT 132   // gemm1 epilogue fp32 staging pitch (mult of 4)

// ---- gemm2 smem (halves): A 128x72, B 128x72, 3-stage ----
#define LDA2 72
#define A2_OFF(s) ((s) * (128 * LDA2))
#define B2_OFF(s) (3 * 128 * LDA2 + (s) * (128 * LDA2))
#define DYNSMEM2 (6 * 128 * LDA2 * 2)                    // 110592 B

typedef wmma::fragment<wmma::matrix_a, 16, 16, 16, __half, wmma::row_major> FragA;
typedef wmma::fragment<wmma::matrix_b, 16, 16, 16, __half, wmma::row_major> FragB;
typedef wmma::fragment<wmma::matrix_b, 16, 16, 16, __half, wmma::col_major> FragBc;
typedef wmma::fragment<wmma::accumulator, 16, 16, 16, float> FragC;

// ======================= prep kernels =======================
__global__ __launch_bounds__(256)
void weights_kernel(const float* __restrict__ U, const float* __restrict__ V) {
    int idx = blockIdx.x * 256 + threadIdx.x;   // < 576*256 = 147456
    g_Vh[idx] = __float2half_rn(V[idx]);        // V flat is already [m][c]
    int o = idx / NM1, m = idx - o * NM1;       // U is [tap][o][r] -> U2[o][m]
    g_U2h[idx] = __float2half_rn(U[(size_t)(m >> 6) * NOC * NR + (size_t)o * NR + (m & 63)]);
}

__global__ __launch_bounds__(256)
void convx_kernel(const float* __restrict__ x) {
    size_t i = ((size_t)blockIdx.x * 256 + threadIdx.x) * 4;   // total 25690112, div by 4
    float4 v = *(const float4*)(x + i);
    __half2 a = __floats2half2_rn(v.x, v.y);
    __half2 b = __floats2half2_rn(v.z, v.w);
    *(uint2*)(g_Xh + i) = make_uint2(*(uint32_t*)&a, *(uint32_t*)&b);
}

// ======================= Stage 1 =======================
// S_t[b][p][m] = sum_c Vh[m][c] * Xh[b][c][p];  4 warps 64x64, 3-stage pipeline over 4 chunks
__global__ __launch_bounds__(128, 2)
void gemm1_kernel() {
    extern __shared__ __half sh[];
    const int t = threadIdx.x, w = t >> 5;
    const int b = blockIdx.z, mBase = blockIdx.x * 128, pBase = blockIdx.y * 128;
    const int warp_m = w & 1, warp_n = w >> 1;
    const __half* X = g_Xh + (size_t)b * NC * NHW;

    FragC acc[4][4];
    #pragma unroll
    for (int i = 0; i < 4; i++)
        #pragma unroll
        for (int j = 0; j < 4; j++) wmma::fill_fragment(acc[i][j], 0.0f);

    auto fill = [&](int ch, int s) {
        const int kBase = ch * 64;
        #pragma unroll
        for (int it = 0; it < 8; it++) {           // A: 128 rows x 8 kgroups
            int idx = it * 128 + t;
            int row = idx >> 3, kg = idx & 7;
            bool v = (mBase + row) < NM1;
            const __half* src = v ? g_Vh + (size_t)(mBase + row) * NC + kBase + kg * 8 : g_Vh;
            cp16(smem_u32(sh + A_OFF(s) + row * LDA + kg * 8), src, v ? 16 : 0);
        }
        #pragma unroll
        for (int it = 0; it < 8; it++) {           // B: 64 rows x 16 pgroups
            int idx = it * 128 + t;
            int row = idx >> 4, pg = idx & 15;
            bool v = (pBase + pg * 8) < NHW;
            const __half* src = v ? X + (size_t)(kBase + row) * NHW + pBase + pg * 8 : X;
            cp16(smem_u32(sh + B_OFF(s) + row * LDB + pg * 8), src, v ? 16 : 0);
        }
    };

    fill(0, 0); CP_COMMIT();
    fill(1, 1); CP_COMMIT();

    for (int ch = 0; ch < 4; ch++) {
        const int s = ch % 3;
        if (ch < 2) { fill(ch + 2, (ch + 2) % 3); CP_COMMIT(); CP_WAIT2(); }
        else if (ch == 2) { CP_WAIT1(); }
        else { CP_WAIT0(); }
        __syncthreads();
        const __half* A  = sh + A_OFF(s);
        const __half* Bm = sh + B_OFF(s);
        #pragma unroll
        for (int kk = 0; kk < 64; kk += 16) {
            FragA a[4];
            FragB bf[4];
            #pragma unroll
            for (int i = 0; i < 4; i++)
                wmma::load_matrix_sync(a[i], A + (warp_m * 64 + i * 16) * LDA + kk, LDA);
            #pragma unroll
            for (int j = 0; j < 4; j++)
                wmma::load_matrix_sync(bf[j], Bm + kk * LDB + warp_n * 64 + j * 16, LDB);
            #pragma unroll
            for (int i = 0; i < 4; i++)
                #pragma unroll
                for (int j = 0; j < 4; j++)
                    wmma::mma_sync(acc[i][j], a[i], bf[j], acc[i][j]);
        }
        __syncthreads();
    }

    // epilogue: col-major frag store -> smem T[p][m] (fp32) -> fp16 coalesced S_t writes
    float* T = (float*)sh;
    #pragma unroll
    for (int i = 0; i < 4; i++)
        #pragma unroll
        for (int j = 0; j < 4; j++)
            wmma::store_matrix_sync(T + (size_t)(warp_n * 64 + j * 16) * LDT + warp_m * 64 + i * 16,
                                    acc[i][j], LDT, wmma::mem_col_major);
    __syncthreads();
    const int mv = NM1 - mBase, pv = NHW - pBase;   // multiples of 64
    const int m8 = (t & 15) * 8;
    const bool mok = m8 < mv;
    #pragma unroll
    for (int it = 0; it < 16; it++) {
        int pl = it * 8 + (t >> 4);
        if (mok && pl < pv) {
            const float* rp = T + (size_t)pl * LDT + m8;
            __half2 h0 = __floats2half2_rn(rp[0], rp[1]);
            __half2 h1 = __floats2half2_rn(rp[2], rp[3]);
            __half2 h2 = __floats2half2_rn(rp[4], rp[5]);
            __half2 h3 = __floats2half2_rn(rp[6], rp[7]);
            uint4 pk = make_uint4(*(uint32_t*)&h0, *(uint32_t*)&h1,
                                  *(uint32_t*)&h2, *(uint32_t*)&h3);
            *(uint4*)(g_St + ((size_t)b * NHW + pBase + pl) * NM1 + mBase + m8) = pk;
        }
    }
}

// ======================= Stage 2 =======================
// Y[b][o][p] = sum_{tap,r} U2h[o][k] * S_t[b][p+shift][k]
// CTA 128x128, 8 warps 64x32 (2x4), 3-stage pipeline over 9 tap-chunks
__global__ __launch_bounds__(256, 2)
void gemm2_kernel(float* __restrict__ y) {
    extern __shared__ __half sh[];
    const int t = threadIdx.x, w = t >> 5;
    const int b = blockIdx.z, oBase = blockIdx.x * 128, pBase = blockIdx.y * 128;
    const int warp_m = w & 1, warp_n = w >> 1;    // 2 x 4 grid of 64x32 tiles
    const __half* S = g_St + (size_t)b * NHW * NM1;

    // per-thread row geometry for the 4 B-rows this thread fills (constant over taps)
    int pr[4], hr[4], wr[4];
    #pragma unroll
    for (int it = 0; it < 4; it++) {
        int row = it * 32 + (t >> 3);
        pr[it] = pBase + row;
        hr[it] = pr[it] / NWID;
        wr[it] = pr[it] - hr[it] * NWID;
    }
    const int kg8 = (t & 7) * 8;

    FragC acc[4][2];
    #pragma unroll
    for (int i = 0; i < 4; i++)
        #pragma unroll
        for (int j = 0; j < 2; j++) wmma::fill_fragment(acc[i][j], 0.0f);

    auto fill = [&](int tap, int s) {
        const int kBase = tap * 64;
        const int di = tap / 3 - 1, dj = tap % 3 - 1;
        const int shift = di * NWID + dj;
        #pragma unroll
        for (int it = 0; it < 4; it++) {           // A: 128 o-rows x 8 groups
            int row = it * 32 + (t >> 3);
            cp16(smem_u32(sh + A2_OFF(s) + row * LDA2 + kg8),
                 g_U2h + (size_t)(oBase + row) * NM1 + kBase + kg8, 16);
        }
        #pragma unroll
        for (int it = 0; it < 4; it++) {           // B: 128 p-rows x 8 groups (m contiguous)
            int row = it * 32 + (t >> 3);
            bool ok = (pr[it] < NHW) && ((unsigned)(hr[it] + di) < (unsigned)NWID)
                                     && ((unsigned)(wr[it] + dj) < (unsigned)NWID);
            const __half* src = ok ? S + (size_t)(pr[it] + shift) * NM1 + kBase + kg8 : g_U2h;
            cp16(smem_u32(sh + B2_OFF(s) + row * LDA2 + kg8), src, ok ? 16 : 0);
        }
    };

    fill(0, 0); CP_COMMIT();
    fill(1, 1); CP_COMMIT();

    for (int ch = 0; ch < 9; ch++) {
        const int s = ch % 3;
        if (ch < 7) { fill(ch + 2, (ch + 2) % 3); CP_COMMIT(); CP_WAIT2(); }
        else if (ch == 7) { CP_WAIT1(); }
        else { CP_WAIT0(); }
        __syncthreads();
        const __half* A  = sh + A2_OFF(s);
        const __half* Bm = sh + B2_OFF(s);
        #pragma unroll
        for (int kk = 0; kk < 64; kk += 16) {
            FragA a[4];
            FragBc bf[2];
            #pragma unroll
            for (int i = 0; i < 4; i++)
                wmma::load_matrix_sync(a[i], A + (warp_m * 64 + i * 16) * LDA2 + kk, LDA2);
            #pragma unroll
            for (int j = 0; j < 2; j++)
                wmma::load_matrix_sync(bf[j], Bm + (size_t)(warp_n * 32 + j * 16) * LDA2 + kk, LDA2);
            #pragma unroll
            for (int i = 0; i < 4; i++)
                #pragma unroll
                for (int j = 0; j < 2; j++)
                    wmma::mma_sync(acc[i][j], a[i], bf[j], acc[i][j]);
        }
        __syncthreads();
    }

    // epilogue: store Y fp32 (o rows always valid; p frags masked at last tile)
    const int pv = NHW - pBase;
    float* C = y + ((size_t)b * NOC + oBase) * NHW + pBase;
    #pragma unroll
    for (int i = 0; i < 4; i++)
        #pragma unroll
        for (int j = 0; j < 2; j++)
            if (warp_n * 32 + j * 16 < pv)
                wmma::store_matrix_sync(
                    C + (size_t)(warp_m * 64 + i * 16) * NHW + warp_n * 32 + j * 16,
                    acc[i][j], NHW, wmma::mem_row_major);
}

// ======================= launch =======================
extern "C" void kernel_launch(void* const* d_in, const int* in_sizes, int n_in,
                              void* d_out, int out_size) {
    const float* x = (const float*)d_in[0];   // [32,256,56,56]
    const float* U = (const float*)d_in[1];   // [3,3,256,64]
    const float* V = (const float*)d_in[2];   // [3,3,64,256]
    float* y = (float*)d_out;                 // [32,256,56,56]

    cudaFuncSetAttribute(gemm1_kernel, cudaFuncAttributeMaxDynamicSharedMemorySize, DYNSMEM1);
    cudaFuncSetAttribute(gemm2_kernel, cudaFuncAttributeMaxDynamicSharedMemorySize, DYNSMEM2);

    weights_kernel<<<576, 256>>>(U, V);
    convx_kernel<<<(NB * NC * NHW) / (256 * 4), 256>>>(x);
    gemm1_kernel<<<dim3(5, 25, 32), 128, DYNSMEM1>>>();   // m fastest: share X tile in L2
    gemm2_kernel<<<dim3(2, 25, 32), 256, DYNSMEM2>>>(y);  // o fastest: share S rows in L2
}

// round 9
// speedup vs baseline: 1.1490x; 1.1490x over previous
#include <cuda_runtime.h>
#include <cuda_fp16.h>
#include <mma.h>
#include <cstdint>
#include <cstddef>

using namespace nvcuda;

#define NB   32
#define NC   256
#define NHW  3136
#define NWID 56
#define NOC  256
#define NR   64
#define NM1  576   // 9 taps * 64 rank

// Device-global scratch (alloc-guard workaround)
__device__ __half g_St[(size_t)NB * NHW * NM1];   // S transposed: [b][p][m] (115 MB) fp16
__device__ __half g_Xh[(size_t)NB * NC * NHW];    // X: [b][c][p] (51 MB) fp16
__device__ __half g_Vh[(size_t)NM1 * NC];         // V: [m][c] fp16
__device__ __half g_U2h[(size_t)NOC * NM1];       // U: [o][m] fp16

// ---------------- helpers ----------------
__device__ __forceinline__ uint32_t smem_u32(const void* p) {
    uint32_t a;
    asm("{ .reg .u64 t; cvta.to.shared.u64 t, %1; cvt.u32.u64 %0, t; }" : "=r"(a) : "l"(p));
    return a;
}
__device__ __forceinline__ void cp16(uint32_t dst, const void* src, int szbytes) {
    asm volatile("cp.async.ca.shared.global [%0], [%1], 16, %2;"
                 :: "r"(dst), "l"(src), "r"(szbytes) : "memory");
}
#define CP_COMMIT() asm volatile("cp.async.commit_group;" ::: "memory")
#define CP_WAIT1()  asm volatile("cp.async.wait_group 1;" ::: "memory")
#define CP_WAIT0()  asm volatile("cp.async.wait_group 0;" ::: "memory")

// ---- gemm1 smem (halves): A 128x72, B 64x136, double buffered ----
#define LDA 72
#define LDB 136
#define A_OFF(buf) ((buf) * (128 * LDA))
#define B_OFF(buf) (2 * 128 * LDA + (buf) * (64 * LDB))
#define DYNSMEM1 73728      // mainloop 71680 B; epilogue T 128*132*4 = 67584 B
#define LDT 132             // gemm1 epilogue fp32 staging pitch (mult of 4)

// ---- gemm2 smem (halves): A 128x72, B 128x72, double buffered ----
#define LDA2 72
#define A2_OFF(buf) ((buf) * (128 * LDA2))
#define B2_OFF(buf) (2 * 128 * LDA2 + (buf) * (128 * LDA2))
#define DYNSMEM2 (4 * 128 * LDA2 * 2)   // 73728 B

typedef wmma::fragment<wmma::matrix_a, 16, 16, 16, __half, wmma::row_major> FragA;
typedef wmma::fragment<wmma::matrix_b, 16, 16, 16, __half, wmma::row_major> FragB;
typedef wmma::fragment<wmma::matrix_b, 16, 16, 16, __half, wmma::col_major> FragBc;
typedef wmma::fragment<wmma::accumulator, 16, 16, 16, float> FragC;

// ======================= prep kernels =======================
__global__ __launch_bounds__(256)
void weights_kernel(const float* __restrict__ U, const float* __restrict__ V) {
    int idx = blockIdx.x * 256 + threadIdx.x;   // < 576*256 = 147456
    g_Vh[idx] = __float2half_rn(V[idx]);        // V flat is already [m][c]
    int o = idx / NM1, m = idx - o * NM1;       // U is [tap][o][r] -> U2[o][m]
    g_U2h[idx] = __float2half_rn(U[(size_t)(m >> 6) * NOC * NR + (size_t)o * NR + (m & 63)]);
}

__global__ __launch_bounds__(256)
void convx_kernel(const float* __restrict__ x) {
    size_t i = ((size_t)blockIdx.x * 256 + threadIdx.x) * 4;   // total 25690112, div by 4
    float4 v = *(const float4*)(x + i);
    __half2 a = __floats2half2_rn(v.x, v.y);
    __half2 b = __floats2half2_rn(v.z, v.w);
    *(uint2*)(g_Xh + i) = make_uint2(*(uint32_t*)&a, *(uint32_t*)&b);
}

// ======================= Stage 1 =======================
// S_t[b][p][m] = sum_c Vh[m][c] * Xh[b][c][p];  4 warps 64x64, 2-stage (R7 config, measured best)
__global__ __launch_bounds__(128, 2)
void gemm1_kernel() {
    extern __shared__ __half sh[];
    const int t = threadIdx.x, w = t >> 5;
    const int b = blockIdx.z, mBase = blockIdx.x * 128, pBase = blockIdx.y * 128;
    const int warp_m = w & 1, warp_n = w >> 1;
    const __half* X = g_Xh + (size_t)b * NC * NHW;

    FragC acc[4][4];
    #pragma unroll
    for (int i = 0; i < 4; i++)
        #pragma unroll
        for (int j = 0; j < 4; j++) wmma::fill_fragment(acc[i][j], 0.0f);

    auto fillA = [&](int kBase, int buf) {
        #pragma unroll
        for (int it = 0; it < 8; it++) {           // 128 rows x 8 groups of 8 halves
            int idx = it * 128 + t;
            int row = idx >> 3, kg = idx & 7;
            bool v = (mBase + row) < NM1;
            const __half* src = v ? g_Vh + (size_t)(mBase + row) * NC + kBase + kg * 8 : g_Vh;
            cp16(smem_u32(sh + A_OFF(buf) + row * LDA + kg * 8), src, v ? 16 : 0);
        }
    };
    auto fillB = [&](int kBase, int buf) {
        #pragma unroll
        for (int it = 0; it < 8; it++) {           // 64 rows x 16 groups of 8 halves
            int idx = it * 128 + t;
            int row = idx >> 4, pg = idx & 15;
            bool v = (pBase + pg * 8) < NHW;
            const __half* src = v ? X + (size_t)(kBase + row) * NHW + pBase + pg * 8 : X;
            cp16(smem_u32(sh + B_OFF(buf) + row * LDB + pg * 8), src, v ? 16 : 0);
        }
    };

    fillA(0, 0); fillB(0, 0); CP_COMMIT();

    for (int ch = 0; ch < 4; ch++) {
        const int buf = ch & 1;
        if (ch < 3) {
            fillA((ch + 1) * 64, buf ^ 1);
            fillB((ch + 1) * 64, buf ^ 1);
            CP_COMMIT();
            CP_WAIT1();
        } else {
            CP_WAIT0();
        }
        __syncthreads();
        const __half* A  = sh + A_OFF(buf);
        const __half* Bm = sh + B_OFF(buf);
        #pragma unroll
        for (int kk = 0; kk < 64; kk += 16) {
            FragA a[4];
            FragB bf[4];
            #pragma unroll
            for (int i = 0; i < 4; i++)
                wmma::load_matrix_sync(a[i], A + (warp_m * 64 + i * 16) * LDA + kk, LDA);
            #pragma unroll
            for (int j = 0; j < 4; j++)
                wmma::load_matrix_sync(bf[j], Bm + kk * LDB + warp_n * 64 + j * 16, LDB);
            #pragma unroll
            for (int i = 0; i < 4; i++)
                #pragma unroll
                for (int j = 0; j < 4; j++)
                    wmma::mma_sync(acc[i][j], a[i], bf[j], acc[i][j]);
        }
        __syncthreads();
    }

    // epilogue: col-major frag store -> smem T[p][m] (fp32) -> fp16 coalesced S_t writes
    float* T = (float*)sh;
    #pragma unroll
    for (int i = 0; i < 4; i++)
        #pragma unroll
        for (int j = 0; j < 4; j++)
            wmma::store_matrix_sync(T + (size_t)(warp_n * 64 + j * 16) * LDT + warp_m * 64 + i * 16,
                                    acc[i][j], LDT, wmma::mem_col_major);
    __syncthreads();
    const int mv = NM1 - mBase, pv = NHW - pBase;   // multiples of 64
    const int m8 = (t & 15) * 8;
    const bool mok = m8 < mv;
    #pragma unroll
    for (int it = 0; it < 16; it++) {
        int pl = it * 8 + (t >> 4);
        if (mok && pl < pv) {
            const float* rp = T + (size_t)pl * LDT + m8;
            __half2 h0 = __floats2half2_rn(rp[0], rp[1]);
            __half2 h1 = __floats2half2_rn(rp[2], rp[3]);
            __half2 h2 = __floats2half2_rn(rp[4], rp[5]);
            __half2 h3 = __floats2half2_rn(rp[6], rp[7]);
            uint4 pk = make_uint4(*(uint32_t*)&h0, *(uint32_t*)&h1,
                                  *(uint32_t*)&h2, *(uint32_t*)&h3);
            *(uint4*)(g_St + ((size_t)b * NHW + pBase + pl) * NM1 + mBase + m8) = pk;
        }
    }
}

// ======================= Stage 2 =======================
// Y[b][o][p] = sum_{tap,r} U2h[o][k] * S_t[b][p+shift][k]
// 128-thread CTAs, 4 warps in 2x2 grid of 64x64 tiles, 2-stage over 9 tap-chunks
__global__ __launch_bounds__(128, 2)
void gemm2_kernel(float* __restrict__ y) {
    extern __shared__ __half sh[];
    const int t = threadIdx.x, w = t >> 5;
    const int b = blockIdx.z, oBase = blockIdx.x * 128, pBase = blockIdx.y * 128;
    const int warp_m = w & 1, warp_n = w >> 1;    // 2 x 2 grid of 64x64 tiles
    const __half* S = g_St + (size_t)b * NHW * NM1;
    const int kg8 = (t & 7) * 8;
    const int rlo = t >> 3;                        // 0..15

    // Precompute per-row-slot geometry: row = it*16 + rlo (it<8); 9-bit tap validity mask
    int     rbase[8];    // pr * NM1  (B source row base)
    uint32_t tmask[8];   // bit tap set if (pr,tap) valid
    #pragma unroll
    for (int it = 0; it < 8; it++) {
        int pr = pBase + it * 16 + rlo;
        int hh = pr / NWID, ww = pr - hh * NWID;
        rbase[it] = pr * NM1;
        uint32_t m = 0;
        #pragma unroll
        for (int tap = 0; tap < 9; tap++) {
            int di = tap / 3 - 1, dj = tap % 3 - 1;
            bool ok = (pr < NHW) && ((unsigned)(hh + di) < (unsigned)NWID)
                                 && ((unsigned)(ww + dj) < (unsigned)NWID);
            m |= (uint32_t)ok << tap;
        }
        tmask[it] = m;
    }

    FragC acc[4][4];
    #pragma unroll
    for (int i = 0; i < 4; i++)
        #pragma unroll
        for (int j = 0; j < 4; j++) wmma::fill_fragment(acc[i][j], 0.0f);

    auto fill = [&](int tap, int buf) {
        const int kBase = tap * 64;
        const int di = tap / 3 - 1, dj = tap % 3 - 1;
        const int soff = (di * NWID + dj) * NM1 + kBase + kg8;   // per-tap scalar + kg8
        #pragma unroll
        for (int it = 0; it < 8; it++) {           // A: 128 o-rows x 8 kgroups
            int row = it * 16 + rlo;
            cp16(smem_u32(sh + A2_OFF(buf) + row * LDA2 + kg8),
                 g_U2h + (size_t)(oBase + row) * NM1 + kBase + kg8, 16);
        }
        #pragma unroll
        for (int it = 0; it < 8; it++) {           // B: 128 p-rows x 8 kgroups (m contiguous)
            int row = it * 16 + rlo;
            bool ok = (tmask[it] >> tap) & 1;
            const __half* src = ok ? S + rbase[it] + soff : g_U2h;
            cp16(smem_u32(sh + B2_OFF(buf) + row * LDA2 + kg8), src, ok ? 16 : 0);
        }
    };

    fill(0, 0); CP_COMMIT();

    for (int ch = 0; ch < 9; ch++) {
        const int buf = ch & 1;
        if (ch < 8) {
            fill(ch + 1, buf ^ 1);
            CP_COMMIT();
            CP_WAIT1();
        } else {
            CP_WAIT0();
        }
        __syncthreads();
        const __half* A  = sh + A2_OFF(buf);
        const __half* Bm = sh + B2_OFF(buf);
        #pragma unroll
        for (int kk = 0; kk < 64; kk += 16) {
            FragA a[4];
            FragBc bf[4];
            #pragma unroll
            for (int i = 0; i < 4; i++)
                wmma::load_matrix_sync(a[i], A + (warp_m * 64 + i * 16) * LDA2 + kk, LDA2);
            #pragma unroll
            for (int j = 0; j < 4; j++)
                wmma::load_matrix_sync(bf[j], Bm + (size_t)(warp_n * 64 + j * 16) * LDA2 + kk, LDA2);
            #pragma unroll
            for (int i = 0; i < 4; i++)
                #pragma unroll
                for (int j = 0; j < 4; j++)
                    wmma::mma_sync(acc[i][j], a[i], bf[j], acc[i][j]);
        }
        __syncthreads();
    }

    // epilogue: store Y fp32 (o rows always valid; p frags masked at last tile)
    const int pv = NHW - pBase;
    float* C = y + ((size_t)b * NOC + oBase) * NHW + pBase;
    #pragma unroll
    for (int i = 0; i < 4; i++)
        #pragma unroll
        for (int j = 0; j < 4; j++)
            if (warp_n * 64 + j * 16 < pv)
                wmma::store_matrix_sync(
                    C + (size_t)(warp_m * 64 + i * 16) * NHW + warp_n * 64 + j * 16,
                    acc[i][j], NHW, wmma::mem_row_major);
}

// ======================= launch =======================
extern "C" void kernel_launch(void* const* d_in, const int* in_sizes, int n_in,
                              void* d_out, int out_size) {
    const float* x = (const float*)d_in[0];   // [32,256,56,56]
    const float* U = (const float*)d_in[1];   // [3,3,256,64]
    const float* V = (const float*)d_in[2];   // [3,3,64,256]
    float* y = (float*)d_out;                 // [32,256,56,56]

    cudaFuncSetAttribute(gemm1_kernel, cudaFuncAttributeMaxDynamicSharedMemorySize, DYNSMEM1);
    cudaFuncSetAttribute(gemm2_kernel, cudaFuncAttributeMaxDynamicSharedMemorySize, DYNSMEM2);

    weights_kernel<<<576, 256>>>(U, V);
    convx_kernel<<<(NB * NC * NHW) / (256 * 4), 256>>>(x);
    gemm1_kernel<<<dim3(5, 25, 32), 128, DYNSMEM1>>>();   // m fastest: share X tile in L2
    gemm2_kernel<<<dim3(2, 25, 32), 128, DYNSMEM2>>>(y);  // o fastest: share S rows in L2
}